// round 10
// baseline (speedup 1.0000x reference)
#include <cuda_runtime.h>

// LengthRegulator, pointer-table form:
//   out[b, f, :] = xs[b, searchsorted(cumsum(ds[b]), f, right), :]
//   (0 if f >= total); all-zero ds rows treated as all-ones.
// B=32, T=512, D=384, MAX_FRAMES=2048.

#define BB 32
#define TT 512
#define DD 384
#define MF 2048
#define D4 (DD / 4)        // 96 float4 per frame
#define NFR (BB * MF)      // 65536 global frames
#define GTHR 192           // 2 x 96 lanes
#define FPBLK 8            // frames per gather block
#define GBLKS (NFR / FPBLK)// 8192 blocks
#define STHR 256           // scan threads (2 tokens each)

// Per-frame source row pointer (as integer). Padding frames point at zrow.
__device__ unsigned long long g_ptr[NFR];
// Zero row for padding frames (static zero-init, never written => deterministic).
__device__ float4 zrow[D4];

// ---------------------------------------------------------------------------
// Kernel A: per-batch inclusive scan + single-pass per-frame pointer table.
// One block per batch, 256 threads, 2 tokens each. No init sweep: valid
// frames get row pointers from the scatter; the tail [total, MF) is filled
// with the zrow pointer directly.
// ds dtype (int32 vs int64) detected at runtime: durations are in [0,4], so
// an int64 buffer has every odd int32 word == 0. P(false positive) = 0.2^256.
// ---------------------------------------------------------------------------
__global__ void __launch_bounds__(STHR)
lr_scan_kernel(const float4* __restrict__ xs, const int* __restrict__ ds32) {
    const int b    = blockIdx.x;
    const int tid  = threadIdx.x;
    const int lane = tid & 31;
    const int wid  = tid >> 5;                 // 8 warps

    __shared__ int s_warp[8];
    __shared__ int s_off[9];
    __shared__ int s_bad;

    const unsigned long long zptr = (unsigned long long)(size_t)zrow;

    if (tid == 0) s_bad = 0;
    const int samp = ds32[(tid * 128 + 1) & 16383];  // odd int32 words
    __syncthreads();
    if (samp != 0) atomicOr(&s_bad, 1);
    __syncthreads();
    const bool is64 = (s_bad == 0);

    // --- load 2 durations per thread (tokens 2*tid, 2*tid+1) ---
    int d0, d1;
    if (is64) {
        longlong2 p = ((const longlong2*)ds32)[b * (TT / 2) + tid];
        d0 = (int)p.x; d1 = (int)p.y;
    } else {
        int2 p = ((const int2*)ds32)[b * (TT / 2) + tid];
        d0 = p.x; d1 = p.y;
    }

    // --- hierarchical inclusive scan over 512 (2 per thread) ---
    const int sum2 = d0 + d1;
    int incl = sum2;
#pragma unroll
    for (int off = 1; off < 32; off <<= 1) {
        int n = __shfl_up_sync(0xFFFFFFFFu, incl, off);
        if (lane >= off) incl += n;
    }
    if (lane == 31) s_warp[wid] = incl;
    __syncthreads();
    if (wid == 0) {
        int w = (lane < 8) ? s_warp[lane] : 0;
#pragma unroll
        for (int off = 1; off < 8; off <<= 1) {
            int n = __shfl_up_sync(0xFFFFFFFFu, w, off);
            if (lane >= off) w += n;
        }
        if (lane < 8) s_off[lane + 1] = w;
        if (lane == 0) s_off[0] = 0;
    }
    __syncthreads();

    int excl = incl - sum2 + s_off[wid];       // exclusive prefix at token 2*tid
    const int total = s_off[8];

    const unsigned long long rowbase =
        (unsigned long long)(size_t)(xs + (size_t)b * TT * D4);
    const unsigned long long rowstep = (unsigned long long)(D4 * 16);

    int total_eff;
    if (total == 0) {
        // all-zero row => durations all 1 => identity map for f < T
        total_eff = TT;
        g_ptr[b * MF + 2 * tid]     = rowbase + (unsigned long long)(2 * tid) * rowstep;
        g_ptr[b * MF + 2 * tid + 1] = rowbase + (unsigned long long)(2 * tid + 1) * rowstep;
    } else {
        total_eff = total;
        // token 2*tid owns [excl, excl+d0); token 2*tid+1 owns [excl+d0, excl+d0+d1)
        const unsigned long long rp0 = rowbase + (unsigned long long)(2 * tid) * rowstep;
        const unsigned long long rp1 = rp0 + rowstep;
        int en = excl + d0;
        for (int f = excl; f < en; f++) g_ptr[b * MF + f] = rp0;
        excl = en; en += d1;
        for (int f = excl; f < en; f++) g_ptr[b * MF + f] = rp1;
    }

    // tail fill: frames [total_eff, MF) -> zero row
    for (int f = total_eff + tid; f < MF; f += STHR)
        g_ptr[b * MF + f] = zptr;
}

// ---------------------------------------------------------------------------
// Kernel B: bandwidth mover (unchanged from R9 — at the steady-state DRAM
// traffic floor). Block = 192 threads (2 x 96 lanes), 8 frames per block.
// Fixed column per thread; per frame: one warp-uniform pointer load, one
// LDG.128, one streaming STG.128.
// ---------------------------------------------------------------------------
__global__ void __launch_bounds__(GTHR)
lr_gather_kernel(float4* __restrict__ out) {
    const int tid = threadIdx.x;
    const int c   = tid % D4;                  // fixed column (0..95)
    const int sub = tid / D4;                  // 0 or 1
    const int gf0 = blockIdx.x * FPBLK + sub;  // global frame, step 2

    unsigned long long p[4];
#pragma unroll
    for (int k = 0; k < 4; k++)
        p[k] = g_ptr[gf0 + 2 * k];             // warp-uniform broadcast load

    float4 v[4];
#pragma unroll
    for (int k = 0; k < 4; k++)
        v[k] = __ldg((const float4*)(size_t)p[k] + c);

#pragma unroll
    for (int k = 0; k < 4; k++)
        __stcs(&out[(size_t)(gf0 + 2 * k) * D4 + c], v[k]);
}

// ---------------------------------------------------------------------------
extern "C" void kernel_launch(void* const* d_in, const int* in_sizes, int n_in,
                              void* d_out, int out_size) {
    // Select pointers by element count (xs: 6,291,456 floats; ds: 16,384).
    const float* xs;
    const int* ds;
    if (in_sizes[0] > in_sizes[1]) {
        xs = (const float*)d_in[0];  ds = (const int*)d_in[1];
    } else {
        xs = (const float*)d_in[1];  ds = (const int*)d_in[0];
    }
    float4* out = (float4*)d_out;

    lr_scan_kernel<<<BB, STHR>>>((const float4*)xs, ds);
    lr_gather_kernel<<<GBLKS, GTHR>>>(out);
}

// round 11
// speedup vs baseline: 1.0371x; 1.0371x over previous
#include <cuda_runtime.h>

// LengthRegulator, two-kernel form (R8 scan + fixed-column gather):
//   out[b, f, :] = xs[b, searchsorted(cumsum(ds[b]), f, right), :]
//   (0 if f >= total); all-zero ds rows treated as all-ones.
// B=32, T=512, D=384, MAX_FRAMES=2048.

#define BB 32
#define TT 512
#define DD 384
#define MF 2048
#define D4 (DD / 4)        // 96 float4 per frame
#define NFR (BB * MF)      // 65536 global frames
#define GTHR 192           // 2 x 96 lanes
#define FPBLK 8            // frames per gather block
#define GBLKS (NFR / FPBLK)// 8192 blocks

// Frame -> source-token index map; -1 means padding (write zeros).
__device__ int g_idx[NFR];

// ---------------------------------------------------------------------------
// Kernel A (R8-proven shape): per-batch inclusive scan + scatter int32 map.
// One block per batch, 128 threads, 4 tokens each.
// ds dtype (int32 vs int64) detected at runtime: durations are in [0,4], so
// an int64 buffer has every odd int32 word == 0. P(false positive) = 0.2^128.
// ---------------------------------------------------------------------------
__global__ void __launch_bounds__(128) lr_scan_kernel(const int* __restrict__ ds32) {
    const int b    = blockIdx.x;
    const int tid  = threadIdx.x;
    const int lane = tid & 31;
    const int wid  = tid >> 5;                 // 4 warps

    __shared__ int s_warp[4];
    __shared__ int s_off[5];
    __shared__ int s_bad;

    if (tid == 0) s_bad = 0;
    const int samp = ds32[(tid * 256 + 1) & 16383];  // odd int32 words
    // init this batch's g_idx to -1 (512 int4 stores across 128 threads)
#pragma unroll
    for (int k = 0; k < 4; k++)
        ((int4*)g_idx)[b * (MF / 4) + tid + k * 128] = make_int4(-1, -1, -1, -1);
    __syncthreads();
    if (samp != 0) atomicOr(&s_bad, 1);
    __syncthreads();
    const bool is64 = (s_bad == 0);

    // --- load 4 durations per thread (tokens 4*tid .. 4*tid+3) ---
    int d0, d1, d2, d3;
    if (is64) {
        longlong2 p = ((const longlong2*)ds32)[b * (TT / 2) + 2 * tid];
        longlong2 q = ((const longlong2*)ds32)[b * (TT / 2) + 2 * tid + 1];
        d0 = (int)p.x; d1 = (int)p.y; d2 = (int)q.x; d3 = (int)q.y;
    } else {
        int4 p = ((const int4*)ds32)[b * (TT / 4) + tid];
        d0 = p.x; d1 = p.y; d2 = p.z; d3 = p.w;
    }

    // --- hierarchical inclusive scan over 512 (4 per thread) ---
    const int sum4 = d0 + d1 + d2 + d3;
    int incl = sum4;
#pragma unroll
    for (int off = 1; off < 32; off <<= 1) {
        int n = __shfl_up_sync(0xFFFFFFFFu, incl, off);
        if (lane >= off) incl += n;
    }
    if (lane == 31) s_warp[wid] = incl;
    __syncthreads();
    if (wid == 0) {
        int w = (lane < 4) ? s_warp[lane] : 0;
#pragma unroll
        for (int off = 1; off < 4; off <<= 1) {
            int n = __shfl_up_sync(0xFFFFFFFFu, w, off);
            if (lane >= off) w += n;
        }
        if (lane < 4) s_off[lane + 1] = w;
        if (lane == 0) s_off[0] = 0;
    }
    __syncthreads();

    int excl = incl - sum4 + s_off[wid];       // exclusive prefix at token 4*tid
    const int total = s_off[4];

    if (total == 0) {
        // all-zero row => durations all 1 => identity map for f < T
#pragma unroll
        for (int k = 0; k < 4; k++)
            g_idx[b * MF + 4 * tid + k] = 4 * tid + k;
    } else {
        int dd[4] = {d0, d1, d2, d3};
#pragma unroll
        for (int q = 0; q < 4; q++) {
            const int en = excl + dd[q];
            for (int f = excl; f < en; f++)
                g_idx[b * MF + f] = 4 * tid + q;
            excl = en;
        }
    }
}

// ---------------------------------------------------------------------------
// Kernel B: bandwidth mover (R9 fixed-column structure + int32 map).
// Block = 192 threads (2 x 96 lanes), 8 frames per block. Fixed column per
// thread; per frame: warp-uniform idx load, clamped unconditional LDG.128,
// select-zero on pad, streaming STG.128. b = frame >> 11 (MF = 2048).
// ---------------------------------------------------------------------------
__global__ void __launch_bounds__(GTHR)
lr_gather_kernel(const float4* __restrict__ xs, float4* __restrict__ out) {
    const int tid = threadIdx.x;
    const int c   = tid % D4;                  // fixed column (0..95)
    const int sub = tid / D4;                  // 0 or 1
    const int gf0 = blockIdx.x * FPBLK + sub;  // global frame, step 2

    int idx[4];
    const float4* src[4];
#pragma unroll
    for (int k = 0; k < 4; k++) {
        const int gf = gf0 + 2 * k;
        const int b  = gf >> 11;               // gf / MF
        const int raw = g_idx[gf];             // warp-uniform broadcast load
        idx[k] = raw;
        const int safe = raw < 0 ? 0 : raw;    // clamp: always in-bounds
        src[k] = xs + (size_t)(b * TT + safe) * D4 + c;
    }

    float4 v[4];
#pragma unroll
    for (int k = 0; k < 4; k++)
        v[k] = __ldg(src[k]);                  // unconditional LDG.128

#pragma unroll
    for (int k = 0; k < 4; k++) {
        const bool pad = idx[k] < 0;
        v[k].x = pad ? 0.f : v[k].x;
        v[k].y = pad ? 0.f : v[k].y;
        v[k].z = pad ? 0.f : v[k].z;
        v[k].w = pad ? 0.f : v[k].w;
        __stcs(&out[(size_t)(gf0 + 2 * k) * D4 + c], v[k]);
    }
}

// ---------------------------------------------------------------------------
extern "C" void kernel_launch(void* const* d_in, const int* in_sizes, int n_in,
                              void* d_out, int out_size) {
    // Select pointers by element count (xs: 6,291,456 floats; ds: 16,384).
    const float* xs;
    const int* ds;
    if (in_sizes[0] > in_sizes[1]) {
        xs = (const float*)d_in[0];  ds = (const int*)d_in[1];
    } else {
        xs = (const float*)d_in[1];  ds = (const int*)d_in[0];
    }
    float4* out = (float4*)d_out;

    lr_scan_kernel<<<BB, 128>>>(ds);
    lr_gather_kernel<<<GBLKS, GTHR>>>((const float4*)xs, out);
}

// round 12
// speedup vs baseline: 1.1067x; 1.0671x over previous
#include <cuda_runtime.h>

// LengthRegulator, two-kernel form with PDL overlap:
//   out[b, f, :] = xs[b, searchsorted(cumsum(ds[b]), f, right), :]
//   (0 if f >= total); all-zero ds rows treated as all-ones.
// B=32, T=512, D=384, MAX_FRAMES=2048.

#define BB 32
#define TT 512
#define DD 384
#define MF 2048
#define D4 (DD / 4)        // 96 float4 per frame
#define NFR (BB * MF)      // 65536 global frames
#define GTHR 192           // 2 x 96 lanes
#define FPBLK 8            // frames per gather block
#define GBLKS (NFR / FPBLK)// 8192 blocks

// Frame -> source-token index map; -1 means padding (write zeros).
__device__ int g_idx[NFR];

// ---------------------------------------------------------------------------
// Kernel A (R8-proven shape): per-batch inclusive scan + scatter int32 map.
// One block per batch, 128 threads, 4 tokens each.
// ds dtype (int32 vs int64) detected at runtime: durations are in [0,4], so
// an int64 buffer has every odd int32 word == 0. P(false positive) = 0.2^128.
// ---------------------------------------------------------------------------
__global__ void __launch_bounds__(128) lr_scan_kernel(const int* __restrict__ ds32) {
    const int b    = blockIdx.x;
    const int tid  = threadIdx.x;
    const int lane = tid & 31;
    const int wid  = tid >> 5;                 // 4 warps

    __shared__ int s_warp[4];
    __shared__ int s_off[5];
    __shared__ int s_bad;

    if (tid == 0) s_bad = 0;
    const int samp = ds32[(tid * 256 + 1) & 16383];  // odd int32 words
    // init this batch's g_idx to -1 (512 int4 stores across 128 threads)
#pragma unroll
    for (int k = 0; k < 4; k++)
        ((int4*)g_idx)[b * (MF / 4) + tid + k * 128] = make_int4(-1, -1, -1, -1);
    __syncthreads();
    if (samp != 0) atomicOr(&s_bad, 1);
    __syncthreads();
    const bool is64 = (s_bad == 0);

    // --- load 4 durations per thread (tokens 4*tid .. 4*tid+3) ---
    int d0, d1, d2, d3;
    if (is64) {
        longlong2 p = ((const longlong2*)ds32)[b * (TT / 2) + 2 * tid];
        longlong2 q = ((const longlong2*)ds32)[b * (TT / 2) + 2 * tid + 1];
        d0 = (int)p.x; d1 = (int)p.y; d2 = (int)q.x; d3 = (int)q.y;
    } else {
        int4 p = ((const int4*)ds32)[b * (TT / 4) + tid];
        d0 = p.x; d1 = p.y; d2 = p.z; d3 = p.w;
    }

    // --- hierarchical inclusive scan over 512 (4 per thread) ---
    const int sum4 = d0 + d1 + d2 + d3;
    int incl = sum4;
#pragma unroll
    for (int off = 1; off < 32; off <<= 1) {
        int n = __shfl_up_sync(0xFFFFFFFFu, incl, off);
        if (lane >= off) incl += n;
    }
    if (lane == 31) s_warp[wid] = incl;
    __syncthreads();
    if (wid == 0) {
        int w = (lane < 4) ? s_warp[lane] : 0;
#pragma unroll
        for (int off = 1; off < 4; off <<= 1) {
            int n = __shfl_up_sync(0xFFFFFFFFu, w, off);
            if (lane >= off) w += n;
        }
        if (lane < 4) s_off[lane + 1] = w;
        if (lane == 0) s_off[0] = 0;
    }
    __syncthreads();

    int excl = incl - sum4 + s_off[wid];       // exclusive prefix at token 4*tid
    const int total = s_off[4];

    if (total == 0) {
        // all-zero row => durations all 1 => identity map for f < T
#pragma unroll
        for (int k = 0; k < 4; k++)
            g_idx[b * MF + 4 * tid + k] = 4 * tid + k;
    } else {
        int dd[4] = {d0, d1, d2, d3};
#pragma unroll
        for (int q = 0; q < 4; q++) {
            const int en = excl + dd[q];
            for (int f = excl; f < en; f++)
                g_idx[b * MF + f] = 4 * tid + q;
            excl = en;
        }
    }
}

// ---------------------------------------------------------------------------
// Kernel B: bandwidth mover (R11 fixed-column structure), launched with
// programmatic stream serialization: blocks come up concurrently with the
// scan kernel, then gate on cudaGridDependencySynchronize() before touching
// g_idx. Block = 192 threads (2 x 96 lanes), 8 frames per block.
// ---------------------------------------------------------------------------
__global__ void __launch_bounds__(GTHR)
lr_gather_kernel(const float4* __restrict__ xs, float4* __restrict__ out) {
    const int tid = threadIdx.x;
    const int c   = tid % D4;                  // fixed column (0..95)
    const int sub = tid / D4;                  // 0 or 1
    const int gf0 = blockIdx.x * FPBLK + sub;  // global frame, step 2

    // Wait for the scan kernel's writes to be visible (PDL gate).
    cudaGridDependencySynchronize();

    int idx[4];
    const float4* src[4];
#pragma unroll
    for (int k = 0; k < 4; k++) {
        const int gf = gf0 + 2 * k;
        const int b  = gf >> 11;               // gf / MF
        const int raw = g_idx[gf];             // warp-uniform broadcast load
        idx[k] = raw;
        const int safe = raw < 0 ? 0 : raw;    // clamp: always in-bounds
        src[k] = xs + (size_t)(b * TT + safe) * D4 + c;
    }

    float4 v[4];
#pragma unroll
    for (int k = 0; k < 4; k++)
        v[k] = __ldg(src[k]);                  // unconditional LDG.128

#pragma unroll
    for (int k = 0; k < 4; k++) {
        const bool pad = idx[k] < 0;
        v[k].x = pad ? 0.f : v[k].x;
        v[k].y = pad ? 0.f : v[k].y;
        v[k].z = pad ? 0.f : v[k].z;
        v[k].w = pad ? 0.f : v[k].w;
        __stcs(&out[(size_t)(gf0 + 2 * k) * D4 + c], v[k]);
    }
}

// ---------------------------------------------------------------------------
extern "C" void kernel_launch(void* const* d_in, const int* in_sizes, int n_in,
                              void* d_out, int out_size) {
    // Select pointers by element count (xs: 6,291,456 floats; ds: 16,384).
    const float* xs;
    const int* ds;
    if (in_sizes[0] > in_sizes[1]) {
        xs = (const float*)d_in[0];  ds = (const int*)d_in[1];
    } else {
        xs = (const float*)d_in[1];  ds = (const int*)d_in[0];
    }
    float4* out = (float4*)d_out;

    lr_scan_kernel<<<BB, 128>>>(ds);

    // Gather with programmatic dependent launch: overlap its launch/ramp-up
    // with the scan kernel; correctness gated in-kernel by
    // cudaGridDependencySynchronize().
    cudaLaunchAttribute attrs[1];
    attrs[0].id = cudaLaunchAttributeProgrammaticStreamSerialization;
    attrs[0].val.programmaticStreamSerializationAllowed = 1;

    cudaLaunchConfig_t cfg = {};
    cfg.gridDim  = dim3(GBLKS, 1, 1);
    cfg.blockDim = dim3(GTHR, 1, 1);
    cfg.dynamicSmemBytes = 0;
    cfg.stream = 0;
    cfg.attrs = attrs;
    cfg.numAttrs = 1;

    cudaLaunchKernelEx(&cfg, lr_gather_kernel, (const float4*)xs, out);
}